// round 8
// baseline (speedup 1.0000x reference)
#include <cuda_runtime.h>
#include <cuda_bf16.h>

#define TPB 128
#define SPB 128            // samples per block (32 per warp)
#define NBLK 512           // 65536 / 128
#define NCH 16             // 512 cols / 32
#define STAGES 3
#define CHUNK_FLOATS 1024  // 32 rows * 32 cols per warp-chunk (4KB)

// dynamic smem (floats):
//   [0, 12288)        per-warp staging: 4 warps * 3 stages * 1024
//   [12288, 14336)    sWt: 512 float4 (transposed W_pre)
//   [14336, 14848)    szl: 128 float4 (per-sample z)
//   [14848, 14900)    sQc[24], sQs[24], sBpre[4]
#define SMEM_FLOATS 14900
#define SMEM_BYTES  (SMEM_FLOATS * 4)

__device__ __forceinline__ unsigned smem_u32(const void* p) {
    return (unsigned)__cvta_generic_to_shared(p);
}

template<int STRIDE>
__device__ __forceinline__ void ry_gate(float st[16], float c, float s) {
#pragma unroll
    for (int i = 0; i < 16; i++) {
        if ((i & STRIDE) == 0) {
            float a = st[i];
            float b = st[i | STRIDE];
            st[i]          = c * a - s * b;
            st[i | STRIDE] = s * a + c * b;
        }
    }
}

__device__ __forceinline__ void swp(float &a, float &b) { float t = a; a = b; b = t; }

// Issue one 32-row x 32-col chunk for this warp: 8 cp.async per lane.
// Per 4-row group the warp covers 4 x 128B contiguous gmem (fully coalesced).
__device__ __forceinline__ void issue_chunk(float* wbuf, const float* xbase,
                                            int ct, int s, int p) {
    float* dst = wbuf + (ct % STAGES) * CHUNK_FLOATS;
    const float* g = xbase + ct * 32 + p * 4;
#pragma unroll
    for (int i = 0; i < 8; i++) {
        int row = i * 4 + s;
        unsigned sa = smem_u32(dst + row * 32 + p * 4);
        asm volatile("cp.async.cg.shared.global [%0], [%1], 16;\n"
                     :: "r"(sa), "l"(g + (size_t)row * 512));
    }
    asm volatile("cp.async.commit_group;\n");
}

__global__ __launch_bounds__(TPB, 3)
void dqn_fused_kernel(const float* __restrict__ input,   // [65536, 512]
                      const float* __restrict__ Wpre,    // [4, 512]
                      const float* __restrict__ bpre,    // [4]
                      const float* __restrict__ qparams, // [24]
                      const float* __restrict__ Wpost,   // [200, 4]
                      const float* __restrict__ bpost,   // [200]
                      float* __restrict__ out)           // [65536, 200]
{
    extern __shared__ float sm[];
    float*  sm_in  = sm;                          // 4 warps * 3 stages * 1024
    float4* sWt    = (float4*)(sm + 12288);       // 512 float4
    float4* szl    = (float4*)(sm + 14336);       // 128 float4
    float*  sQc    = sm + 14848;
    float*  sQs    = sQc + 24;
    float*  sBpre  = sQs + 24;

    const int t    = threadIdx.x;
    const int lane = t & 31;
    const int wrp  = t >> 5;
    const int p    = lane & 7;     // 16B-column position
    const int s    = lane >> 3;    // row-within-4-row-group
    const int rowBase = blockIdx.x * SPB + wrp * 32;
    const float* xbase = input + (size_t)rowBase * 512;
    float* wbuf = sm_in + wrp * (STAGES * CHUNK_FLOATS);

    // prologue: get 2 chunks in flight immediately
    issue_chunk(wbuf, xbase, 0, s, p);
    issue_chunk(wbuf, xbase, 1, s, p);

    // stage transposed W_pre + params while loads fly
    for (int c = t; c < 512; c += TPB)
        sWt[c] = make_float4(Wpre[c], Wpre[512 + c], Wpre[1024 + c], Wpre[1536 + c]);
    if (t < 24) {
        float a = 0.5f * qparams[t];
        sQc[t] = cosf(a);
        sQs[t] = sinf(a);
    }
    if (t < 4) sBpre[t] = bpre[t];
    __syncthreads();   // the only block barrier

    // ---- main loop: per-warp cp.async pipeline, 2 chunks outstanding ----
    float4 acc[8];
#pragma unroll
    for (int k = 0; k < 8; k++) acc[k] = make_float4(0.f, 0.f, 0.f, 0.f);

#pragma unroll 1
    for (int ct = 0; ct < NCH; ct++) {
        if (ct + 2 < NCH) {
            asm volatile("cp.async.wait_group 1;\n");
            __syncwarp();
            issue_chunk(wbuf, xbase, ct + 2, s, p);   // buffer (ct+2)%3 holds ct-1: free
        } else {
            asm volatile("cp.async.wait_group 0;\n");
            __syncwarp();
        }

        const float* buf = wbuf + (ct % STAGES) * CHUNK_FLOATS;
        const int c4 = ct * 8 + p;                    // global float4-of-columns
        float4 w0 = sWt[4 * c4 + 0];
        float4 w1 = sWt[4 * c4 + 1];
        float4 w2 = sWt[4 * c4 + 2];
        float4 w3 = sWt[4 * c4 + 3];
#pragma unroll
        for (int k = 0; k < 8; k++) {
            const int row = 4 * k + s;
            float4 x = *(const float4*)(buf + row * 32 + p * 4);
            acc[k].x += x.x * w0.x + x.y * w1.x + x.z * w2.x + x.w * w3.x;
            acc[k].y += x.x * w0.y + x.y * w1.y + x.z * w2.y + x.w * w3.y;
            acc[k].z += x.x * w0.z + x.y * w1.z + x.z * w2.z + x.w * w3.z;
            acc[k].w += x.x * w0.w + x.y * w1.w + x.z * w2.w + x.w * w3.w;
        }
        __syncwarp();   // all lanes done with buffer before it is re-filled
    }

    // ---- segment reduction (8 lanes): lane p==k keeps row 4p+s ----
    float4 r = make_float4(0.f, 0.f, 0.f, 0.f);
#pragma unroll
    for (int k = 0; k < 8; k++) {
        float4 a = acc[k];
#pragma unroll
        for (int m = 1; m <= 4; m <<= 1) {
            a.x += __shfl_xor_sync(0xffffffffu, a.x, m);
            a.y += __shfl_xor_sync(0xffffffffu, a.y, m);
            a.z += __shfl_xor_sync(0xffffffffu, a.z, m);
            a.w += __shfl_xor_sync(0xffffffffu, a.w, m);
        }
        if (p == k) r = a;
    }
    const int myRow = 4 * p + s;

    // ---- activation + quantum circuit (state in registers) ----
    const float QPI4 = 0.78539816339744830962f;   // pi/4 = half of pi/2 gate angle
    float c0, s0, c1, s1, c2, s2, c3, s3;
    sincosf(tanhf(r.x + sBpre[0]) * QPI4, &s0, &c0);
    sincosf(tanhf(r.y + sBpre[1]) * QPI4, &s1, &c1);
    sincosf(tanhf(r.z + sBpre[2]) * QPI4, &s2, &c2);
    sincosf(tanhf(r.w + sBpre[3]) * QPI4, &s3, &c3);

    float st[16];
#pragma unroll
    for (int i = 0; i < 16; i++) st[i] = 0.25f;

    ry_gate<8>(st, c0, s0);
    ry_gate<4>(st, c1, s1);
    ry_gate<2>(st, c2, s2);
    ry_gate<1>(st, c3, s3);

#pragma unroll
    for (int k = 0; k < 6; k++) {
        // CNOT(0,1), CNOT(2,3), CNOT(1,2)  (pure register permutations)
        swp(st[8], st[12]); swp(st[9], st[13]); swp(st[10], st[14]); swp(st[11], st[15]);
        swp(st[2], st[3]);  swp(st[6], st[7]);  swp(st[10], st[11]); swp(st[14], st[15]);
        swp(st[4], st[6]);  swp(st[5], st[7]);  swp(st[12], st[14]); swp(st[13], st[15]);
        ry_gate<8>(st, sQc[4 * k + 0], sQs[4 * k + 0]);
        ry_gate<4>(st, sQc[4 * k + 1], sQs[4 * k + 1]);
        ry_gate<2>(st, sQc[4 * k + 2], sQs[4 * k + 2]);
        ry_gate<1>(st, sQc[4 * k + 3], sQs[4 * k + 3]);
    }

    float z0 = 0.f, z1 = 0.f, z2 = 0.f, z3 = 0.f;
#pragma unroll
    for (int i = 0; i < 16; i++) {
        float pp = st[i] * st[i];
        z0 += (i & 8) ? -pp : pp;
        z1 += (i & 4) ? -pp : pp;
        z2 += (i & 2) ? -pp : pp;
        z3 += (i & 1) ? -pp : pp;
    }

    szl[wrp * 32 + myRow] = make_float4(z0, z1, z2, z3);
    __syncwarp();   // warp-local: each warp consumes only its own 32 entries

    // ---- warp-cooperative coalesced epilogue ----
    const float4* wp4 = (const float4*)Wpost;
    const float4* bp4 = (const float4*)bpost;

    float4 wa0 = wp4[4 * lane + 0];
    float4 wa1 = wp4[4 * lane + 1];
    float4 wa2 = wp4[4 * lane + 2];
    float4 wa3 = wp4[4 * lane + 3];
    float4 ba  = bp4[lane];

    const bool hasB = (lane < 18);
    const int cb = 32 + lane;
    float4 wb0, wb1, wb2, wb3, bb;
    if (hasB) {
        wb0 = wp4[4 * cb + 0];
        wb1 = wp4[4 * cb + 1];
        wb2 = wp4[4 * cb + 2];
        wb3 = wp4[4 * cb + 3];
        bb  = bp4[cb];
    }

#pragma unroll 4
    for (int rr = 0; rr < 32; rr++) {
        float4 zv = szl[wrp * 32 + rr];                 // broadcast LDS
        float4* orow = (float4*)(out + (size_t)(rowBase + rr) * 200);
        float4 o;
        o.x = ba.x + zv.x * wa0.x + zv.y * wa0.y + zv.z * wa0.z + zv.w * wa0.w;
        o.y = ba.y + zv.x * wa1.x + zv.y * wa1.y + zv.z * wa1.z + zv.w * wa1.w;
        o.z = ba.z + zv.x * wa2.x + zv.y * wa2.y + zv.z * wa2.z + zv.w * wa2.w;
        o.w = ba.w + zv.x * wa3.x + zv.y * wa3.y + zv.z * wa3.z + zv.w * wa3.w;
        __stcs(orow + lane, o);                         // contiguous 512B per warp
        if (hasB) {
            float4 q;
            q.x = bb.x + zv.x * wb0.x + zv.y * wb0.y + zv.z * wb0.z + zv.w * wb0.w;
            q.y = bb.y + zv.x * wb1.x + zv.y * wb1.y + zv.z * wb1.z + zv.w * wb1.w;
            q.z = bb.z + zv.x * wb2.x + zv.y * wb2.y + zv.z * wb2.z + zv.w * wb2.w;
            q.w = bb.w + zv.x * wb3.x + zv.y * wb3.y + zv.z * wb3.z + zv.w * wb3.w;
            __stcs(orow + cb, q);
        }
    }
}

extern "C" void kernel_launch(void* const* d_in, const int* in_sizes, int n_in,
                              void* d_out, int out_size)
{
    const float* input   = (const float*)d_in[0];  // [65536,512]
    const float* Wpre    = (const float*)d_in[1];  // [4,512]
    const float* bpre    = (const float*)d_in[2];  // [4]
    const float* qparams = (const float*)d_in[3];  // [24]
    const float* Wpost   = (const float*)d_in[4];  // [200,4]
    const float* bpost   = (const float*)d_in[5];  // [200]
    float* out = (float*)d_out;                    // [65536,200]

    cudaFuncSetAttribute(dqn_fused_kernel,
                         cudaFuncAttributeMaxDynamicSharedMemorySize, SMEM_BYTES);
    dqn_fused_kernel<<<NBLK, TPB, SMEM_BYTES>>>(input, Wpre, bpre, qparams,
                                                Wpost, bpost, out);
}

// round 9
// speedup vs baseline: 1.1012x; 1.1012x over previous
#include <cuda_runtime.h>
#include <cuda_bf16.h>

#define TPB 128
#define SPB 64             // samples per block (16 per warp)
#define NBLK 1024          // 65536 / 64

template<int STRIDE>
__device__ __forceinline__ void ry_gate(float st[16], float c, float s) {
#pragma unroll
    for (int i = 0; i < 16; i++) {
        if ((i & STRIDE) == 0) {
            float a = st[i];
            float b = st[i | STRIDE];
            st[i]          = c * a - s * b;
            st[i | STRIDE] = s * a + c * b;
        }
    }
}

__device__ __forceinline__ void swp(float &a, float &b) { float t = a; a = b; b = t; }

// Plain 256-bit global load (sm_100+). 32B per lane.
__device__ __forceinline__ void ldg256(const float* ptr, float x[8]) {
    unsigned r0, r1, r2, r3, r4, r5, r6, r7;
    asm volatile("ld.global.nc.v8.b32 {%0,%1,%2,%3,%4,%5,%6,%7}, [%8];"
                 : "=r"(r0), "=r"(r1), "=r"(r2), "=r"(r3),
                   "=r"(r4), "=r"(r5), "=r"(r6), "=r"(r7)
                 : "l"(ptr));
    x[0] = __uint_as_float(r0); x[1] = __uint_as_float(r1);
    x[2] = __uint_as_float(r2); x[3] = __uint_as_float(r3);
    x[4] = __uint_as_float(r4); x[5] = __uint_as_float(r5);
    x[6] = __uint_as_float(r6); x[7] = __uint_as_float(r7);
}

__global__ __launch_bounds__(TPB)
void dqn_fused_kernel(const float* __restrict__ input,   // [65536, 512]
                      const float* __restrict__ Wpre,    // [4, 512]
                      const float* __restrict__ bpre,    // [4]
                      const float* __restrict__ qparams, // [24]
                      const float* __restrict__ Wpost,   // [200, 4]
                      const float* __restrict__ bpost,   // [200]
                      float* __restrict__ out)           // [65536, 200]
{
    __shared__ float4 sWt[512];     // Wt[c] = {W[0][c],W[1][c],W[2][c],W[3][c]}
    __shared__ float4 szl[SPB];     // per-sample z
    __shared__ float  sQc[24], sQs[24], sBpre[4];

    const int t = threadIdx.x;

    // ---- stage transposed W_pre + small params (one-time, tiny) ----
    for (int c = t; c < 512; c += TPB)
        sWt[c] = make_float4(Wpre[c], Wpre[512 + c], Wpre[1024 + c], Wpre[1536 + c]);
    if (t < 24) {
        float a = 0.5f * qparams[t];
        sQc[t] = cosf(a);
        sQs[t] = sinf(a);
    }
    if (t < 4) sBpre[t] = bpre[t];
    __syncthreads();   // the only block barrier

    const int lane = t & 31;
    const int wrp  = t >> 5;
    const int p    = lane & 7;     // 32B-chunk position within segment
    const int s    = lane >> 3;    // row-within-4-row-group
    const int rowBase = blockIdx.x * SPB + wrp * 16;   // warp's first global row
    const float* xbase = input + (size_t)rowBase * 512;

    // ---- warp-cooperative pre-GEMM ----
    // per jj: lane covers cols [64jj+8p, 64jj+8p+8) for 4 rows.
    // 4 back-to-back v8 loads per lane = 128B outstanding/lane = 4KB/warp.
    float4 acc[4];
#pragma unroll
    for (int k = 0; k < 4; k++) acc[k] = make_float4(0.f, 0.f, 0.f, 0.f);

#pragma unroll 1
    for (int jj = 0; jj < 8; jj++) {
        const int cbase = jj * 64 + p * 8;    // first column this lane handles

        // batch the 4 independent row loads first (maximize MLP)
        float x0[8], x1[8], x2[8], x3[8];
        ldg256(xbase + (size_t)(0 + s) * 512 + cbase, x0);
        ldg256(xbase + (size_t)(4 + s) * 512 + cbase, x1);
        ldg256(xbase + (size_t)(8 + s) * 512 + cbase, x2);
        ldg256(xbase + (size_t)(12 + s) * 512 + cbase, x3);

        // W for these 8 columns (broadcast LDS.128, reused across 4 rows)
        float4 w[8];
#pragma unroll
        for (int i = 0; i < 8; i++) w[i] = sWt[cbase + i];

#pragma unroll
        for (int i = 0; i < 8; i++) {
            acc[0].x += x0[i] * w[i].x;  acc[0].y += x0[i] * w[i].y;
            acc[0].z += x0[i] * w[i].z;  acc[0].w += x0[i] * w[i].w;
            acc[1].x += x1[i] * w[i].x;  acc[1].y += x1[i] * w[i].y;
            acc[1].z += x1[i] * w[i].z;  acc[1].w += x1[i] * w[i].w;
            acc[2].x += x2[i] * w[i].x;  acc[2].y += x2[i] * w[i].y;
            acc[2].z += x2[i] * w[i].z;  acc[2].w += x2[i] * w[i].w;
            acc[3].x += x3[i] * w[i].x;  acc[3].y += x3[i] * w[i].y;
            acc[3].z += x3[i] * w[i].z;  acc[3].w += x3[i] * w[i].w;
        }
    }

    // ---- 8-lane segment reduction; all lanes hold each sum afterwards.
    //      Lane takes k = p&3 (lanes p and p+4 duplicate the same row). ----
    float4 r;
#pragma unroll
    for (int k = 0; k < 4; k++) {
        float4 a = acc[k];
#pragma unroll
        for (int m = 1; m <= 4; m <<= 1) {
            a.x += __shfl_xor_sync(0xffffffffu, a.x, m);
            a.y += __shfl_xor_sync(0xffffffffu, a.y, m);
            a.z += __shfl_xor_sync(0xffffffffu, a.z, m);
            a.w += __shfl_xor_sync(0xffffffffu, a.w, m);
        }
        if ((p & 3) == k) r = a;
    }
    const int myRow = 4 * (p & 3) + s;   // row (within warp's 16) this lane owns

    // ---- activation + quantum circuit (state in registers) ----
    const float QPI4 = 0.78539816339744830962f;   // pi/4 = half of pi/2 gate angle
    float c0, s0, c1, s1, c2, s2, c3, s3;
    sincosf(tanhf(r.x + sBpre[0]) * QPI4, &s0, &c0);
    sincosf(tanhf(r.y + sBpre[1]) * QPI4, &s1, &c1);
    sincosf(tanhf(r.z + sBpre[2]) * QPI4, &s2, &c2);
    sincosf(tanhf(r.w + sBpre[3]) * QPI4, &s3, &c3);

    float st[16];
#pragma unroll
    for (int i = 0; i < 16; i++) st[i] = 0.25f;

    ry_gate<8>(st, c0, s0);
    ry_gate<4>(st, c1, s1);
    ry_gate<2>(st, c2, s2);
    ry_gate<1>(st, c3, s3);

#pragma unroll
    for (int k = 0; k < 6; k++) {
        // CNOT(0,1), CNOT(2,3), CNOT(1,2)  (pure register permutations)
        swp(st[8], st[12]); swp(st[9], st[13]); swp(st[10], st[14]); swp(st[11], st[15]);
        swp(st[2], st[3]);  swp(st[6], st[7]);  swp(st[10], st[11]); swp(st[14], st[15]);
        swp(st[4], st[6]);  swp(st[5], st[7]);  swp(st[12], st[14]); swp(st[13], st[15]);
        ry_gate<8>(st, sQc[4 * k + 0], sQs[4 * k + 0]);
        ry_gate<4>(st, sQc[4 * k + 1], sQs[4 * k + 1]);
        ry_gate<2>(st, sQc[4 * k + 2], sQs[4 * k + 2]);
        ry_gate<1>(st, sQc[4 * k + 3], sQs[4 * k + 3]);
    }

    float z0 = 0.f, z1 = 0.f, z2 = 0.f, z3 = 0.f;
#pragma unroll
    for (int i = 0; i < 16; i++) {
        float pp = st[i] * st[i];
        z0 += (i & 8) ? -pp : pp;
        z1 += (i & 4) ? -pp : pp;
        z2 += (i & 2) ? -pp : pp;
        z3 += (i & 1) ? -pp : pp;
    }

    if (p < 4) szl[wrp * 16 + myRow] = make_float4(z0, z1, z2, z3);
    __syncwarp();   // warp-local: each warp consumes only its own 16 entries

    // ---- warp-cooperative coalesced epilogue ----
    // lane owns output float4 columns {lane} and {32+lane | lane<18}
    const float4* wp4 = (const float4*)Wpost;   // row c of W_post = one float4
    const float4* bp4 = (const float4*)bpost;

    float4 wa0 = wp4[4 * lane + 0];
    float4 wa1 = wp4[4 * lane + 1];
    float4 wa2 = wp4[4 * lane + 2];
    float4 wa3 = wp4[4 * lane + 3];
    float4 ba  = bp4[lane];

    const bool hasB = (lane < 18);
    const int cb = 32 + lane;
    float4 wb0, wb1, wb2, wb3, bb;
    if (hasB) {
        wb0 = wp4[4 * cb + 0];
        wb1 = wp4[4 * cb + 1];
        wb2 = wp4[4 * cb + 2];
        wb3 = wp4[4 * cb + 3];
        bb  = bp4[cb];
    }

#pragma unroll 4
    for (int rr = 0; rr < 16; rr++) {
        float4 zv = szl[wrp * 16 + rr];                 // broadcast LDS
        float4* orow = (float4*)(out + (size_t)(rowBase + rr) * 200);
        float4 o;
        o.x = ba.x + zv.x * wa0.x + zv.y * wa0.y + zv.z * wa0.z + zv.w * wa0.w;
        o.y = ba.y + zv.x * wa1.x + zv.y * wa1.y + zv.z * wa1.z + zv.w * wa1.w;
        o.z = ba.z + zv.x * wa2.x + zv.y * wa2.y + zv.z * wa2.z + zv.w * wa2.w;
        o.w = ba.w + zv.x * wa3.x + zv.y * wa3.y + zv.z * wa3.z + zv.w * wa3.w;
        __stcs(orow + lane, o);                         // contiguous 512B per warp
        if (hasB) {
            float4 q;
            q.x = bb.x + zv.x * wb0.x + zv.y * wb0.y + zv.z * wb0.z + zv.w * wb0.w;
            q.y = bb.y + zv.x * wb1.x + zv.y * wb1.y + zv.z * wb1.z + zv.w * wb1.w;
            q.z = bb.z + zv.x * wb2.x + zv.y * wb2.y + zv.z * wb2.z + zv.w * wb2.w;
            q.w = bb.w + zv.x * wb3.x + zv.y * wb3.y + zv.z * wb3.z + zv.w * wb3.w;
            __stcs(orow + cb, q);
        }
    }
}

extern "C" void kernel_launch(void* const* d_in, const int* in_sizes, int n_in,
                              void* d_out, int out_size)
{
    const float* input   = (const float*)d_in[0];  // [65536,512]
    const float* Wpre    = (const float*)d_in[1];  // [4,512]
    const float* bpre    = (const float*)d_in[2];  // [4]
    const float* qparams = (const float*)d_in[3];  // [24]
    const float* Wpost   = (const float*)d_in[4];  // [200,4]
    const float* bpost   = (const float*)d_in[5];  // [200]
    float* out = (float*)d_out;                    // [65536,200]

    dqn_fused_kernel<<<NBLK, TPB>>>(input, Wpre, bpre, qparams, Wpost, bpost, out);
}

// round 10
// speedup vs baseline: 1.1419x; 1.0370x over previous
#include <cuda_runtime.h>
#include <cuda_bf16.h>

#define TPB 256
#define SPB 128            // samples per block
#define NBLK 512           // 65536 / 128
#define CH_ROWS 32
#define CH_BYTES 65536     // 32 rows * 2KB
#define CH_FLOATS 16384
#define NCHUNK 4           // 128 rows / 32
#define STAGES 3

// dynamic smem layout (floats):
//   [0, 49152)       3 stage buffers (3 * 16384) = 192KB
//   [49152, 49664)   szl: 128 float4
//   [49664, 49670)   mbar[3] (u64, byte 198656: 8-aligned)
//   [49670, 49718)   sQc[24], sQs[24]
//   [49718, 49722)   sBpre[4]
#define SMEM_BYTES 198912

__device__ __forceinline__ unsigned su32(const void* p) {
    return (unsigned)__cvta_generic_to_shared(p);
}

template<int STRIDE>
__device__ __forceinline__ void ry_gate(float st[16], float c, float s) {
#pragma unroll
    for (int i = 0; i < 16; i++) {
        if ((i & STRIDE) == 0) {
            float a = st[i];
            float b = st[i | STRIDE];
            st[i]          = c * a - s * b;
            st[i | STRIDE] = s * a + c * b;
        }
    }
}

__device__ __forceinline__ void swp(float &a, float &b) { float t = a; a = b; b = t; }

__device__ __forceinline__ void mbar_wait(unsigned mb, unsigned parity) {
    asm volatile(
        "{\n\t"
        ".reg .pred P;\n\t"
        "WAIT_%=: \n\t"
        "mbarrier.try_wait.parity.acquire.cta.shared::cta.b64 P, [%0], %1;\n\t"
        "@P bra DONE_%=;\n\t"
        "bra WAIT_%=;\n\t"
        "DONE_%=: \n\t"
        "}"
        :: "r"(mb), "r"(parity) : "memory");
}

__device__ __forceinline__ void issue_bulk(unsigned mb, float* dst, const float* src) {
    asm volatile("mbarrier.arrive.expect_tx.shared.b64 _, [%0], %1;"
                 :: "r"(mb), "r"(CH_BYTES) : "memory");
    asm volatile("cp.async.bulk.shared::cta.global.mbarrier::complete_tx::bytes "
                 "[%0], [%1], %2, [%3];"
                 :: "r"(su32(dst)), "l"(src), "r"(CH_BYTES), "r"(mb) : "memory");
}

__global__ __launch_bounds__(TPB, 1)
void dqn_fused_kernel(const float* __restrict__ input,   // [65536, 512]
                      const float* __restrict__ Wpre,    // [4, 512]
                      const float* __restrict__ bpre,    // [4]
                      const float* __restrict__ qparams, // [24]
                      const float* __restrict__ Wpost,   // [200, 4]
                      const float* __restrict__ bpost,   // [200]
                      float* __restrict__ out)           // [65536, 200]
{
    extern __shared__ float sm[];
    float*  bufs  = sm;                               // 3 * CH_FLOATS
    float4* szl   = (float4*)(sm + 3 * CH_FLOATS);    // 128
    unsigned long long* mbar = (unsigned long long*)(sm + 3 * CH_FLOATS + 512);
    float*  sQc   = sm + 3 * CH_FLOATS + 512 + 6;
    float*  sQs   = sQc + 24;
    float*  sBpre = sQs + 24;

    const int t    = threadIdx.x;
    const int lane = t & 31;
    const int wrp  = t >> 5;
    const int blockBase = blockIdx.x * SPB;

    if (t == 0) {
#pragma unroll
        for (int i = 0; i < STAGES; i++)
            asm volatile("mbarrier.init.shared.b64 [%0], 1;"
                         :: "r"(su32(&mbar[i])) : "memory");
    }
    if (t < 24) {
        float a = 0.5f * qparams[t];
        sQc[t] = cosf(a);
        sQs[t] = sinf(a);
    }
    if (t < 4) sBpre[t] = bpre[t];
    __syncthreads();   // mbar init + params visible

    // kick 3 bulk copies: 192KB in flight from one thread, zero registers
    if (t == 0) {
#pragma unroll
        for (int c = 0; c < STAGES; c++)
            issue_bulk(su32(&mbar[c]), bufs + c * CH_FLOATS,
                       input + (size_t)(blockBase + c * CH_ROWS) * 512);
    }

    // ---- W_pre into registers: lane owns cols [16*lane, 16*lane+16),
    //      pre-rotated by s so the inner loop is statically indexed ----
    const int s  = (lane >> 1) & 3;
    const int c0 = lane * 16;
    float4 wr[4][4];   // wr[k][i] = outputs for col c0 + 4*((k+s)&3) + i
#pragma unroll
    for (int k = 0; k < 4; k++) {
        const int cb = c0 + 4 * ((k + s) & 3);
#pragma unroll
        for (int i = 0; i < 4; i++) {
            const int c = cb + i;
            wr[k][i] = make_float4(__ldg(Wpre + c),        __ldg(Wpre + 512 + c),
                                   __ldg(Wpre + 1024 + c), __ldg(Wpre + 1536 + c));
        }
    }

    // ---- main loop over 4 chunks of 32 rows; warp handles 4 rows per chunk ----
    float rsx = 0.f, rsy = 0.f, rsz = 0.f, rsw = 0.f;   // kept presums (lanes<16)

#pragma unroll 1
    for (int ct = 0; ct < NCHUNK; ct++) {
        const unsigned mb = su32(&mbar[ct % STAGES]);
        mbar_wait(mb, (unsigned)((ct / STAGES) & 1));

        const float* buf = bufs + (ct % STAGES) * CH_FLOATS + (wrp * 4) * 512;

        float4 acc[4];
#pragma unroll
        for (int r = 0; r < 4; r++) acc[r] = make_float4(0.f, 0.f, 0.f, 0.f);

#pragma unroll
        for (int j = 0; j < 4; j++) {
            const int off = c0 + 4 * ((j + s) & 3);   // swizzled: conflict-free LDS.128
            float4 xv[4];
#pragma unroll
            for (int r = 0; r < 4; r++)
                xv[r] = *(const float4*)(buf + r * 512 + off);
#pragma unroll
            for (int r = 0; r < 4; r++) {
                acc[r].x += xv[r].x * wr[j][0].x + xv[r].y * wr[j][1].x
                          + xv[r].z * wr[j][2].x + xv[r].w * wr[j][3].x;
                acc[r].y += xv[r].x * wr[j][0].y + xv[r].y * wr[j][1].y
                          + xv[r].z * wr[j][2].y + xv[r].w * wr[j][3].y;
                acc[r].z += xv[r].x * wr[j][0].z + xv[r].y * wr[j][1].z
                          + xv[r].z * wr[j][2].z + xv[r].w * wr[j][3].z;
                acc[r].w += xv[r].x * wr[j][0].w + xv[r].y * wr[j][1].w
                          + xv[r].z * wr[j][2].w + xv[r].w * wr[j][3].w;
            }
        }

        // full-warp reduction per row; lane ct*4+r keeps its sample's presum
#pragma unroll
        for (int r = 0; r < 4; r++) {
            float ax = acc[r].x, ay = acc[r].y, az = acc[r].z, aw = acc[r].w;
#pragma unroll
            for (int m = 1; m <= 16; m <<= 1) {
                ax += __shfl_xor_sync(0xffffffffu, ax, m);
                ay += __shfl_xor_sync(0xffffffffu, ay, m);
                az += __shfl_xor_sync(0xffffffffu, az, m);
                aw += __shfl_xor_sync(0xffffffffu, aw, m);
            }
            if (lane == ct * 4 + r) { rsx = ax; rsy = ay; rsz = az; rsw = aw; }
        }

        if (ct == 0) {
            __syncthreads();              // all warps done with stage 0
            if (t == 0) {
                asm volatile("fence.proxy.async.shared::cta;" ::: "memory");
                issue_bulk(su32(&mbar[0]), bufs,
                           input + (size_t)(blockBase + 3 * CH_ROWS) * 512);
            }
        }
    }

    // ---- circuit: lane l<16 owns sample localRow = (l>>2)*32 + wrp*4 + (l&3) ----
    if (lane < 16) {
        const float QPI4 = 0.78539816339744830962f;   // pi/4 (half of pi/2 angle)
        float c0g, s0g, c1g, s1g, c2g, s2g, c3g, s3g;
        sincosf(tanhf(rsx + sBpre[0]) * QPI4, &s0g, &c0g);
        sincosf(tanhf(rsy + sBpre[1]) * QPI4, &s1g, &c1g);
        sincosf(tanhf(rsz + sBpre[2]) * QPI4, &s2g, &c2g);
        sincosf(tanhf(rsw + sBpre[3]) * QPI4, &s3g, &c3g);

        float st[16];
#pragma unroll
        for (int i = 0; i < 16; i++) st[i] = 0.25f;

        ry_gate<8>(st, c0g, s0g);
        ry_gate<4>(st, c1g, s1g);
        ry_gate<2>(st, c2g, s2g);
        ry_gate<1>(st, c3g, s3g);

#pragma unroll
        for (int k = 0; k < 6; k++) {
            // CNOT(0,1), CNOT(2,3), CNOT(1,2) — register permutations
            swp(st[8], st[12]); swp(st[9], st[13]); swp(st[10], st[14]); swp(st[11], st[15]);
            swp(st[2], st[3]);  swp(st[6], st[7]);  swp(st[10], st[11]); swp(st[14], st[15]);
            swp(st[4], st[6]);  swp(st[5], st[7]);  swp(st[12], st[14]); swp(st[13], st[15]);
            ry_gate<8>(st, sQc[4 * k + 0], sQs[4 * k + 0]);
            ry_gate<4>(st, sQc[4 * k + 1], sQs[4 * k + 1]);
            ry_gate<2>(st, sQc[4 * k + 2], sQs[4 * k + 2]);
            ry_gate<1>(st, sQc[4 * k + 3], sQs[4 * k + 3]);
        }

        float z0 = 0.f, z1 = 0.f, z2 = 0.f, z3 = 0.f;
#pragma unroll
        for (int i = 0; i < 16; i++) {
            float pp = st[i] * st[i];
            z0 += (i & 8) ? -pp : pp;
            z1 += (i & 4) ? -pp : pp;
            z2 += (i & 2) ? -pp : pp;
            z3 += (i & 1) ? -pp : pp;
        }

        const int localRow = (lane >> 2) * 32 + wrp * 4 + (lane & 3);
        szl[localRow] = make_float4(z0, z1, z2, z3);
    }
    __syncthreads();

    // ---- warp-cooperative coalesced epilogue: warp outputs rows [wrp*16, wrp*16+16) ----
    const float4* wp4 = (const float4*)Wpost;
    const float4* bp4 = (const float4*)bpost;

    float4 wa0 = wp4[4 * lane + 0];
    float4 wa1 = wp4[4 * lane + 1];
    float4 wa2 = wp4[4 * lane + 2];
    float4 wa3 = wp4[4 * lane + 3];
    float4 ba  = bp4[lane];

    const bool hasB = (lane < 18);
    const int cb = 32 + lane;
    float4 wb0, wb1, wb2, wb3, bb;
    if (hasB) {
        wb0 = wp4[4 * cb + 0];
        wb1 = wp4[4 * cb + 1];
        wb2 = wp4[4 * cb + 2];
        wb3 = wp4[4 * cb + 3];
        bb  = bp4[cb];
    }

    const int rowBase = blockBase + wrp * 16;
#pragma unroll 4
    for (int rr = 0; rr < 16; rr++) {
        float4 zv = szl[wrp * 16 + rr];                 // broadcast LDS
        float4* orow = (float4*)(out + (size_t)(rowBase + rr) * 200);
        float4 o;
        o.x = ba.x + zv.x * wa0.x + zv.y * wa0.y + zv.z * wa0.z + zv.w * wa0.w;
        o.y = ba.y + zv.x * wa1.x + zv.y * wa1.y + zv.z * wa1.z + zv.w * wa1.w;
        o.z = ba.z + zv.x * wa2.x + zv.y * wa2.y + zv.z * wa2.z + zv.w * wa2.w;
        o.w = ba.w + zv.x * wa3.x + zv.y * wa3.y + zv.z * wa3.z + zv.w * wa3.w;
        __stcs(orow + lane, o);                         // contiguous 512B per warp
        if (hasB) {
            float4 q;
            q.x = bb.x + zv.x * wb0.x + zv.y * wb0.y + zv.z * wb0.z + zv.w * wb0.w;
            q.y = bb.y + zv.x * wb1.x + zv.y * wb1.y + zv.z * wb1.z + zv.w * wb1.w;
            q.z = bb.z + zv.x * wb2.x + zv.y * wb2.y + zv.z * wb2.z + zv.w * wb2.w;
            q.w = bb.w + zv.x * wb3.x + zv.y * wb3.y + zv.z * wb3.z + zv.w * wb3.w;
            __stcs(orow + cb, q);
        }
    }
}

extern "C" void kernel_launch(void* const* d_in, const int* in_sizes, int n_in,
                              void* d_out, int out_size)
{
    const float* input   = (const float*)d_in[0];  // [65536,512]
    const float* Wpre    = (const float*)d_in[1];  // [4,512]
    const float* bpre    = (const float*)d_in[2];  // [4]
    const float* qparams = (const float*)d_in[3];  // [24]
    const float* Wpost   = (const float*)d_in[4];  // [200,4]
    const float* bpost   = (const float*)d_in[5];  // [200]
    float* out = (float*)d_out;                    // [65536,200]

    cudaFuncSetAttribute(dqn_fused_kernel,
                         cudaFuncAttributeMaxDynamicSharedMemorySize, SMEM_BYTES);
    dqn_fused_kernel<<<NBLK, TPB, SMEM_BYTES>>>(input, Wpre, bpre, qparams,
                                                Wpost, bpost, out);
}

// round 12
// speedup vs baseline: 1.2155x; 1.0644x over previous
#include <cuda_runtime.h>
#include <cuda_bf16.h>

#define TPB 256
#define SPB 128            // samples per block
#define NBLK 512           // 65536 / 128
#define CH_ROWS 16
#define CH_BYTES 32768     // 16 rows * 2KB
#define CH_FLOATS 8192
#define NCHUNK 8           // 128 rows / 16
#define STAGES 3

// dynamic smem layout (floats):
//   [0, 24576)       3 stage buffers (3 * 8192) = 96KB
//   [24576, 25088)   szl: 128 float4
//   [25088, 25094)   mbar[3] (u64, 8B aligned: byte 100352)
//   [25094, 25146)   sQc[24], sQs[24], sBpre[4]
#define SMEM_BYTES 100608

__device__ __forceinline__ unsigned su32(const void* p) {
    return (unsigned)__cvta_generic_to_shared(p);
}

template<int STRIDE>
__device__ __forceinline__ void ry_gate(float st[16], float c, float s) {
#pragma unroll
    for (int i = 0; i < 16; i++) {
        if ((i & STRIDE) == 0) {
            float a = st[i];
            float b = st[i | STRIDE];
            st[i]          = c * a - s * b;
            st[i | STRIDE] = s * a + c * b;
        }
    }
}

__device__ __forceinline__ void swp(float &a, float &b) { float t = a; a = b; b = t; }

__device__ __forceinline__ void mbar_wait(unsigned mb, unsigned parity) {
    asm volatile(
        "{\n\t"
        ".reg .pred P;\n\t"
        "WAIT_%=: \n\t"
        "mbarrier.try_wait.parity.acquire.cta.shared::cta.b64 P, [%0], %1;\n\t"
        "@P bra DONE_%=;\n\t"
        "bra WAIT_%=;\n\t"
        "DONE_%=: \n\t"
        "}"
        :: "r"(mb), "r"(parity) : "memory");
}

__device__ __forceinline__ void issue_bulk(unsigned mb, float* dst, const float* src) {
    asm volatile("mbarrier.arrive.expect_tx.shared.b64 _, [%0], %1;"
                 :: "r"(mb), "r"(CH_BYTES) : "memory");
    asm volatile("cp.async.bulk.shared::cta.global.mbarrier::complete_tx::bytes "
                 "[%0], [%1], %2, [%3];"
                 :: "r"(su32(dst)), "l"(src), "r"(CH_BYTES), "r"(mb) : "memory");
}

__global__ __launch_bounds__(TPB, 2)
void dqn_fused_kernel(const float* __restrict__ input,   // [65536, 512]
                      const float* __restrict__ Wpre,    // [4, 512]
                      const float* __restrict__ bpre,    // [4]
                      const float* __restrict__ qparams, // [24]
                      const float* __restrict__ Wpost,   // [200, 4]
                      const float* __restrict__ bpost,   // [200]
                      float* __restrict__ out)           // [65536, 200]
{
    extern __shared__ float sm[];
    float*  bufs  = sm;                               // 3 * CH_FLOATS
    float4* szl   = (float4*)(sm + 3 * CH_FLOATS);    // 128
    unsigned long long* mbar = (unsigned long long*)(sm + 3 * CH_FLOATS + 512);
    float*  sQc   = sm + 3 * CH_FLOATS + 512 + 6;
    float*  sQs   = sQc + 24;
    float*  sBpre = sQs + 24;

    const int t    = threadIdx.x;
    const int lane = t & 31;
    const int wrp  = t >> 5;
    const int blockBase = blockIdx.x * SPB;

    if (t == 0) {
#pragma unroll
        for (int i = 0; i < STAGES; i++)
            asm volatile("mbarrier.init.shared.b64 [%0], 1;"
                         :: "r"(su32(&mbar[i])) : "memory");
    }
    if (t < 24) {
        float a = 0.5f * qparams[t];
        sQc[t] = cosf(a);
        sQs[t] = sinf(a);
    }
    if (t < 4) sBpre[t] = bpre[t];
    __syncthreads();   // mbar init + params visible

    // kick 3 bulk copies (96KB) from one thread; zero register cost
    if (t == 0) {
#pragma unroll
        for (int c = 0; c < STAGES; c++)
            issue_bulk(su32(&mbar[c]), bufs + c * CH_FLOATS,
                       input + (size_t)(blockBase + c * CH_ROWS) * 512);
    }

    // ---- W_pre in registers: lane owns cols {128j + 4*lane + i}, j<4, i<4 ----
    float4 wr[4][4];
#pragma unroll
    for (int j = 0; j < 4; j++) {
#pragma unroll
        for (int i = 0; i < 4; i++) {
            const int c = 128 * j + 4 * lane + i;
            wr[j][i] = make_float4(__ldg(Wpre + c),        __ldg(Wpre + 512 + c),
                                   __ldg(Wpre + 1024 + c), __ldg(Wpre + 1536 + c));
        }
    }

    // ---- main loop: 8 chunks of 16 rows; warp computes 2 rows per chunk ----
    float rsx = 0.f, rsy = 0.f, rsz = 0.f, rsw = 0.f;   // kept presums (lanes<16)

#pragma unroll 1
    for (int ct = 0; ct < NCHUNK; ct++) {
        const unsigned mb = su32(&mbar[ct % STAGES]);
        mbar_wait(mb, (unsigned)((ct / STAGES) & 1));

        const float* buf = bufs + (ct % STAGES) * CH_FLOATS + (wrp * 2) * 512;

        float4 acc[2];
        acc[0] = make_float4(0.f, 0.f, 0.f, 0.f);
        acc[1] = make_float4(0.f, 0.f, 0.f, 0.f);

#pragma unroll
        for (int j = 0; j < 4; j++) {
            // conflict-free: whole warp reads one contiguous 512B span per LDS.128
            float4 xv0 = *(const float4*)(buf +       128 * j + 4 * lane);
            float4 xv1 = *(const float4*)(buf + 512 + 128 * j + 4 * lane);
            acc[0].x += xv0.x * wr[j][0].x + xv0.y * wr[j][1].x
                      + xv0.z * wr[j][2].x + xv0.w * wr[j][3].x;
            acc[0].y += xv0.x * wr[j][0].y + xv0.y * wr[j][1].y
                      + xv0.z * wr[j][2].y + xv0.w * wr[j][3].y;
            acc[0].z += xv0.x * wr[j][0].z + xv0.y * wr[j][1].z
                      + xv0.z * wr[j][2].z + xv0.w * wr[j][3].z;
            acc[0].w += xv0.x * wr[j][0].w + xv0.y * wr[j][1].w
                      + xv0.z * wr[j][2].w + xv0.w * wr[j][3].w;
            acc[1].x += xv1.x * wr[j][0].x + xv1.y * wr[j][1].x
                      + xv1.z * wr[j][2].x + xv1.w * wr[j][3].x;
            acc[1].y += xv1.x * wr[j][0].y + xv1.y * wr[j][1].y
                      + xv1.z * wr[j][2].y + xv1.w * wr[j][3].y;
            acc[1].z += xv1.x * wr[j][0].z + xv1.y * wr[j][1].z
                      + xv1.z * wr[j][2].z + xv1.w * wr[j][3].z;
            acc[1].w += xv1.x * wr[j][0].w + xv1.y * wr[j][1].w
                      + xv1.z * wr[j][2].w + xv1.w * wr[j][3].w;
        }

        // 5-round bfly reduction per row; keeper lane = ct*2 + r
#pragma unroll
        for (int r = 0; r < 2; r++) {
            float ax = acc[r].x, ay = acc[r].y, az = acc[r].z, aw = acc[r].w;
#pragma unroll
            for (int m = 1; m <= 16; m <<= 1) {
                ax += __shfl_xor_sync(0xffffffffu, ax, m);
                ay += __shfl_xor_sync(0xffffffffu, ay, m);
                az += __shfl_xor_sync(0xffffffffu, az, m);
                aw += __shfl_xor_sync(0xffffffffu, aw, m);
            }
            if (lane == ct * 2 + r) { rsx = ax; rsy = ay; rsz = az; rsw = aw; }
        }

        __syncthreads();   // all warps done with this stage buffer
        if (t == 0 && ct + STAGES < NCHUNK) {
            asm volatile("fence.proxy.async.shared::cta;" ::: "memory");
            issue_bulk(mb, bufs + (ct % STAGES) * CH_FLOATS,
                       input + (size_t)(blockBase + (ct + STAGES) * CH_ROWS) * 512);
        }
    }

    // ---- circuit: lane l<16 owns sample localRow = (l>>1)*16 + wrp*2 + (l&1) ----
    if (lane < 16) {
        const float QPI4 = 0.78539816339744830962f;   // pi/4 (half of pi/2 angle)
        float c0g, s0g, c1g, s1g, c2g, s2g, c3g, s3g;
        sincosf(tanhf(rsx + sBpre[0]) * QPI4, &s0g, &c0g);
        sincosf(tanhf(rsy + sBpre[1]) * QPI4, &s1g, &c1g);
        sincosf(tanhf(rsz + sBpre[2]) * QPI4, &s2g, &c2g);
        sincosf(tanhf(rsw + sBpre[3]) * QPI4, &s3g, &c3g);

        float st[16];
#pragma unroll
        for (int i = 0; i < 16; i++) st[i] = 0.25f;

        ry_gate<8>(st, c0g, s0g);
        ry_gate<4>(st, c1g, s1g);
        ry_gate<2>(st, c2g, s2g);
        ry_gate<1>(st, c3g, s3g);

#pragma unroll
        for (int k = 0; k < 6; k++) {
            // CNOT(0,1), CNOT(2,3), CNOT(1,2) — register permutations
            swp(st[8], st[12]); swp(st[9], st[13]); swp(st[10], st[14]); swp(st[11], st[15]);
            swp(st[2], st[3]);  swp(st[6], st[7]);  swp(st[10], st[11]); swp(st[14], st[15]);
            swp(st[4], st[6]);  swp(st[5], st[7]);  swp(st[12], st[14]); swp(st[13], st[15]);
            ry_gate<8>(st, sQc[4 * k + 0], sQs[4 * k + 0]);
            ry_gate<4>(st, sQc[4 * k + 1], sQs[4 * k + 1]);
            ry_gate<2>(st, sQc[4 * k + 2], sQs[4 * k + 2]);
            ry_gate<1>(st, sQc[4 * k + 3], sQs[4 * k + 3]);
        }

        float z0 = 0.f, z1 = 0.f, z2 = 0.f, z3 = 0.f;
#pragma unroll
        for (int i = 0; i < 16; i++) {
            float pp = st[i] * st[i];
            z0 += (i & 8) ? -pp : pp;
            z1 += (i & 4) ? -pp : pp;
            z2 += (i & 2) ? -pp : pp;
            z3 += (i & 1) ? -pp : pp;
        }

        const int localRow = (lane >> 1) * 16 + wrp * 2 + (lane & 1);
        szl[localRow] = make_float4(z0, z1, z2, z3);
    }
    __syncthreads();

    // ---- warp-cooperative coalesced epilogue: warp outputs rows [wrp*16, +16) ----
    const float4* wp4 = (const float4*)Wpost;
    const float4* bp4 = (const float4*)bpost;

    float4 wa0 = wp4[4 * lane + 0];
    float4 wa1 = wp4[4 * lane + 1];
    float4 wa2 = wp4[4 * lane + 2];
    float4 wa3 = wp4[4 * lane + 3];
    float4 ba  = bp4[lane];

    const bool hasB = (lane < 18);
    const int cb = 32 + lane;
    float4 wb0, wb1, wb2, wb3, bb;
    if (hasB) {
        wb0 = wp4[4 * cb + 0];
        wb1 = wp4[4 * cb + 1];
        wb2 = wp4[4 * cb + 2];
        wb3 = wp4[4 * cb + 3];
        bb  = bp4[cb];
    }

    const int rowBase = blockBase + wrp * 16;
#pragma unroll 4
    for (int rr = 0; rr < 16; rr++) {
        float4 zv = szl[wrp * 16 + rr];                 // broadcast LDS
        float4* orow = (float4*)(out + (size_t)(rowBase + rr) * 200);
        float4 o;
        o.x = ba.x + zv.x * wa0.x + zv.y * wa0.y + zv.z * wa0.z + zv.w * wa0.w;
        o.y = ba.y + zv.x * wa1.x + zv.y * wa1.y + zv.z * wa1.z + zv.w * wa1.w;
        o.z = ba.z + zv.x * wa2.x + zv.y * wa2.y + zv.z * wa2.z + zv.w * wa2.w;
        o.w = ba.w + zv.x * wa3.x + zv.y * wa3.y + zv.z * wa3.z + zv.w * wa3.w;
        __stcs(orow + lane, o);                         // contiguous 512B per warp
        if (hasB) {
            float4 q;
            q.x = bb.x + zv.x * wb0.x + zv.y * wb0.y + zv.z * wb0.z + zv.w * wb0.w;
            q.y = bb.y + zv.x * wb1.x + zv.y * wb1.y + zv.z * wb1.z + zv.w * wb1.w;
            q.z = bb.z + zv.x * wb2.x + zv.y * wb2.y + zv.z * wb2.z + zv.w * wb2.w;
            q.w = bb.w + zv.x * wb3.x + zv.y * wb3.y + zv.z * wb3.z + zv.w * wb3.w;
            __stcs(orow + cb, q);
        }
    }
}

extern "C" void kernel_launch(void* const* d_in, const int* in_sizes, int n_in,
                              void* d_out, int out_size)
{
    const float* input   = (const float*)d_in[0];  // [65536,512]
    const float* Wpre    = (const float*)d_in[1];  // [4,512]
    const float* bpre    = (const float*)d_in[2];  // [4]
    const float* qparams = (const float*)d_in[3];  // [24]
    const float* Wpost   = (const float*)d_in[4];  // [200,4]
    const float* bpost   = (const float*)d_in[5];  // [200]
    float* out = (float*)d_out;                    // [65536,200]

    cudaFuncSetAttribute(dqn_fused_kernel,
                         cudaFuncAttributeMaxDynamicSharedMemorySize, SMEM_BYTES);
    dqn_fused_kernel<<<NBLK, TPB, SMEM_BYTES>>>(input, Wpre, bpre, qparams,
                                                Wpost, bpost, out);
}